// round 4
// baseline (speedup 1.0000x reference)
#include <cuda_runtime.h>
#include <math.h>

#define W  2048
#define H  2048
#define NIMG 16

#define STRIP_OUT 120            // output columns per warp strip
#define NSTRIPS   18             // ceil(2048/120)
#define ROWT      128            // output rows per warp job
#define NROWT     16             // 2048/128
#define WARPS_PER_BLOCK 8
#define NJOBS (NIMG * NROWT * NSTRIPS)          // 4608
#define NBLOCKS (NJOBS / WARPS_PER_BLOCK)       // 576

__device__ __forceinline__ float4 ld_row(const float* __restrict__ im,
                                         int y, int c0, bool colok)
{
    if (!((unsigned)y < (unsigned)H) || !colok) return make_float4(0.f, 0.f, 0.f, 0.f);
    return *reinterpret_cast<const float4*>(im + (size_t)y * W + c0);
}

// One pipeline step. PH is a literal 0/1/2 so all %3 indices constant-fold;
// DO_* are literals in the warmup and `true` in the steady loop.
#define BODY(IY, PH, DO_SM, DO_E, DO_ST) do {                                    \
    const int y_ = y0 - 3 + (IY);                                                \
    float4 cur = nx;                                                             \
    nx = ld_row(im, y_ + 1, c0, colok);                                          \
    {                                                                            \
        float inm1 = __shfl_up_sync(0xffffffffu, cur.w, 1);                      \
        float inp4 = __shfl_down_sync(0xffffffffu, cur.x, 1);                    \
        h[(PH)][0] = inm1  + 2.f*cur.x + cur.y;                                  \
        h[(PH)][1] = cur.x + 2.f*cur.y + cur.z;                                  \
        h[(PH)][2] = cur.y + 2.f*cur.z + cur.w;                                  \
        h[(PH)][3] = cur.z + 2.f*cur.w + inp4;                                   \
    }                                                                            \
    if (DO_SM) {                                                                 \
        const int ys_ = y_ - 1;                                                  \
        const float msk = ((unsigned)ys_ < (unsigned)H) ? colmul : 0.f;          \
        float sm[4];                                                             \
        _Pragma("unroll") for (int j = 0; j < 4; j++)                            \
            sm[j] = (h[((PH)+1)%3][j] + 2.f*h[((PH)+2)%3][j] + h[(PH)][j]) * msk;\
        float smm1 = __shfl_up_sync(0xffffffffu, sm[3], 1);                      \
        float smp4 = __shfl_down_sync(0xffffffffu, sm[0], 1);                    \
        p[(PH)][0] = sm[1] - smm1;  q[(PH)][0] = smm1  + 2.f*sm[0] + sm[1];      \
        p[(PH)][1] = sm[2] - sm[0]; q[(PH)][1] = sm[0] + 2.f*sm[1] + sm[2];      \
        p[(PH)][2] = sm[3] - sm[1]; q[(PH)][2] = sm[1] + 2.f*sm[2] + sm[3];      \
        p[(PH)][3] = smp4  - sm[2]; q[(PH)][3] = sm[2] + 2.f*sm[3] + smp4;       \
        if (DO_E) {                                                              \
            _Pragma("unroll") for (int j = 0; j < 4; j++) {                      \
                float gx = p[((PH)+1)%3][j] + 2.f*p[((PH)+2)%3][j] + p[(PH)][j]; \
                float gy = q[(PH)][j] - q[((PH)+1)%3][j];                        \
                e[(PH)][j] = sqrtf(gx*gx + gy*gy);                               \
            }                                                                    \
            float el = __shfl_up_sync(0xffffffffu, e[(PH)][3], 1);               \
            float er = __shfl_down_sync(0xffffffffu, e[(PH)][0], 1);             \
            m[(PH)][0] = fmaxf(fmaxf(el,         e[(PH)][0]), e[(PH)][1]);       \
            m[(PH)][1] = fmaxf(fmaxf(e[(PH)][0], e[(PH)][1]), e[(PH)][2]);       \
            m[(PH)][2] = fmaxf(fmaxf(e[(PH)][1], e[(PH)][2]), e[(PH)][3]);       \
            m[(PH)][3] = fmaxf(fmaxf(e[(PH)][2], e[(PH)][3]), er);               \
            s[(PH)][0] = fmaxf(el,         e[(PH)][1]);                          \
            s[(PH)][1] = fmaxf(e[(PH)][0], e[(PH)][2]);                          \
            s[(PH)][2] = fmaxf(e[(PH)][1], e[(PH)][3]);                          \
            s[(PH)][3] = fmaxf(e[(PH)][2], er);                                  \
            if ((DO_ST) && storer) {                                             \
                const int yo_ = y_ - 3;                                          \
                const bool irow = (yo_ > 0) && (yo_ < H - 1);                    \
                float r[4];                                                      \
                _Pragma("unroll") for (int j = 0; j < 4; j++) {                  \
                    float c  = e[((PH)+2)%3][j];                                 \
                    float nm = fmaxf(fmaxf(m[((PH)+1)%3][j], m[(PH)][j]),        \
                                     s[((PH)+2)%3][j]);                          \
                    r[j] = (irow && icol[j] && (c < nm)) ? 0.f : c;              \
                }                                                                \
                *reinterpret_cast<float4*>(op + (size_t)yo_ * W + c0) =          \
                    make_float4(r[0], r[1], r[2], r[3]);                         \
            }                                                                    \
        }                                                                        \
    }                                                                            \
} while (0)

__global__ __launch_bounds__(256, 2)
void edge_kernel(const float* __restrict__ img, float* __restrict__ out)
{
    const int lane = threadIdx.x & 31;
    const int warp = threadIdx.x >> 5;
    const int job  = blockIdx.x * WARPS_PER_BLOCK + warp;

    const int strip = job % NSTRIPS;
    const int t     = job / NSTRIPS;
    const int rowt  = t % NROWT;
    const int n     = t / NROWT;

    const int cb = strip * STRIP_OUT - 4;
    const int c0 = cb + lane * 4;
    const int y0 = rowt * ROWT;

    const float* im = img + (size_t)n * H * W;
    float*       op = out + (size_t)n * H * W;

    const bool  colok  = (c0 >= 0) && (c0 < W);
    const bool  storer = (lane >= 1) && (lane <= 30) && colok;
    const float colmul = colok ? 0.0625f : 0.f;

    bool icol[4];
    #pragma unroll
    for (int j = 0; j < 4; j++)
        icol[j] = (c0 + j > 0) && (c0 + j < W - 1);

    float h[3][4], p[3][4], q[3][4], e[3][4], m[3][4], s[3][4];
    #pragma unroll
    for (int a = 0; a < 3; a++)
        #pragma unroll
        for (int j = 0; j < 4; j++) {
            h[a][j]=0.f; p[a][j]=0.f; q[a][j]=0.f;
            e[a][j]=0.f; m[a][j]=0.f; s[a][j]=0.f;
        }

    float4 nx = ld_row(im, y0 - 3, c0, colok);

    // ---- warmup: 8 fully-specialized iterations (stores begin at iy=6) ----
    BODY(0, 0, false, false, false);
    BODY(1, 1, false, false, false);
    BODY(2, 2, true,  false, false);
    BODY(3, 0, true,  false, false);
    BODY(4, 1, true,  true,  false);
    BODY(5, 2, true,  true,  false);
    BODY(6, 0, true,  true,  true);
    BODY(7, 1, true,  true,  true);

    // ---- steady state: iy = 8 .. ROWT+5, branch-free, phases (2,0,1) ----
    // (ROWT+6-8) = 126 iterations = 42 groups of 3
    for (int base = 8; base < ROWT + 6; base += 3) {
        BODY(base + 0, 2, true, true, true);
        BODY(base + 1, 0, true, true, true);
        BODY(base + 2, 1, true, true, true);
    }
}

extern "C" void kernel_launch(void* const* d_in, const int* in_sizes, int n_in,
                              void* d_out, int out_size)
{
    const float* img = (const float*)d_in[0];
    float* out = (float*)d_out;
    edge_kernel<<<NBLOCKS, 256>>>(img, out);
}

// round 5
// speedup vs baseline: 1.4276x; 1.4276x over previous
#include <cuda_runtime.h>
#include <math.h>

#define W  2048
#define H  2048
#define NIMG 16

#define STRIP_OUT 120            // output columns per warp strip
#define NSTRIPS   18             // ceil(2048/120)
#define ROWT      64             // output rows per warp job
#define NROWT     32             // 2048/64
#define WARPS_PER_BLOCK 8
#define NJOBS (NIMG * NROWT * NSTRIPS)          // 9216
#define NBLOCKS (NJOBS / WARPS_PER_BLOCK)       // 1152

__device__ __forceinline__ float4 ld_row(const float* __restrict__ im,
                                         int y, int c0, bool colok)
{
    if (!((unsigned)y < (unsigned)H) || !colok) return make_float4(0.f, 0.f, 0.f, 0.f);
    return *reinterpret_cast<const float4*>(im + (size_t)y * W + c0);
}

__global__ __launch_bounds__(256, 3)
void edge_kernel(const float* __restrict__ img, float* __restrict__ out)
{
    const int lane = threadIdx.x & 31;
    const int warp = threadIdx.x >> 5;
    const int job  = blockIdx.x * WARPS_PER_BLOCK + warp;

    const int strip = job % NSTRIPS;
    const int t     = job / NSTRIPS;
    const int rowt  = t % NROWT;
    const int n     = t / NROWT;

    const int cb = strip * STRIP_OUT - 4;   // loaded column base (mult of 4)
    const int c0 = cb + lane * 4;
    const int y0 = rowt * ROWT;

    const float* im = img + (size_t)n * H * W;
    float*       op = out + (size_t)n * H * W;

    const bool  colok  = (c0 >= 0) && (c0 < W);
    const bool  storer = (lane >= 1) && (lane <= 30) && colok;
    const float colmul = colok ? 0.0625f : 0.f;

    bool icol[4];
    #pragma unroll
    for (int j = 0; j < 4; j++)
        icol[j] = (c0 + j > 0) && (c0 + j < W - 1);

    // register rings: h (horiz gauss), p/q (horiz sobel parts) over 3 rows;
    // e rows for yo and yo+1 only; el/er = e at cols c0-1 / c0+4;
    // m = row max incl center over cols [j-1..j+1].
    float h0[4], h1[4], h2[4];
    float p0[4], p1[4], p2[4];
    float q0[4], q1[4], q2[4];
    float e1[4], e2[4];
    float m0[4], m1[4], m2[4];
    float el1 = 0.f, er1 = 0.f, el2 = 0.f, er2 = 0.f;
    #pragma unroll
    for (int j = 0; j < 4; j++) {
        h0[j]=h1[j]=h2[j]=0.f; p0[j]=p1[j]=p2[j]=0.f; q0[j]=q1[j]=q2[j]=0.f;
        e1[j]=e2[j]=0.f; m0[j]=m1[j]=m2[j]=0.f;
    }

    // 2-deep row prefetch (MLP = 2)
    float4 nx1 = ld_row(im, y0 - 3, c0, colok);
    float4 nx2 = ld_row(im, y0 - 2, c0, colok);

    for (int iy = 0; iy < ROWT + 6; iy++) {
        const int y = y0 - 3 + iy;
        float4 cur = nx1;
        nx1 = nx2;
        nx2 = ld_row(im, y + 2, c0, colok);

        // ---- h(y): horizontal [1,2,1] of input ----
        float inm1 = __shfl_up_sync(0xffffffffu, cur.w, 1);
        float inp4 = __shfl_down_sync(0xffffffffu, cur.x, 1);
        #pragma unroll
        for (int j = 0; j < 4; j++) { h0[j] = h1[j]; h1[j] = h2[j]; }
        h2[0] = inm1  + 2.f*cur.x + cur.y;
        h2[1] = cur.x + 2.f*cur.y + cur.z;
        h2[2] = cur.y + 2.f*cur.z + cur.w;
        h2[3] = cur.z + 2.f*cur.w + inp4;

        if (iy >= 2) {
            // ---- sm(ys = y-1): vertical [1,2,1]/16, zero outside the image
            //      (the reference zero-pads the SMOOTHED tensor for Sobel) ----
            const int ys = y - 1;
            const float msk = ((unsigned)ys < (unsigned)H) ? colmul : 0.f;
            float sm[4];
            #pragma unroll
            for (int j = 0; j < 4; j++)
                sm[j] = (h0[j] + 2.f*h1[j] + h2[j]) * msk;

            float smm1 = __shfl_up_sync(0xffffffffu, sm[3], 1);
            float smp4 = __shfl_down_sync(0xffffffffu, sm[0], 1);

            #pragma unroll
            for (int j = 0; j < 4; j++) { p0[j]=p1[j]; p1[j]=p2[j]; q0[j]=q1[j]; q1[j]=q2[j]; }
            p2[0] = sm[1] - smm1;  q2[0] = smm1  + 2.f*sm[0] + sm[1];
            p2[1] = sm[2] - sm[0]; q2[1] = sm[0] + 2.f*sm[1] + sm[2];
            p2[2] = sm[3] - sm[1]; q2[2] = sm[1] + 2.f*sm[2] + sm[3];
            p2[3] = smp4  - sm[2]; q2[3] = sm[2] + 2.f*sm[3] + smp4;

            if (iy >= 4) {
                // ---- e(ye = y-2) + row maxes ----
                #pragma unroll
                for (int j = 0; j < 4; j++) {
                    e1[j] = e2[j];
                    m0[j] = m1[j]; m1[j] = m2[j];
                }
                el1 = el2; er1 = er2;
                #pragma unroll
                for (int j = 0; j < 4; j++) {
                    float gx = p0[j] + 2.f*p1[j] + p2[j];
                    float gy = q2[j] - q0[j];
                    e2[j] = sqrtf(gx*gx + gy*gy);
                }
                el2 = __shfl_up_sync(0xffffffffu, e2[3], 1);
                er2 = __shfl_down_sync(0xffffffffu, e2[0], 1);

                m2[0] = fmaxf(fmaxf(el2,   e2[0]), e2[1]);
                m2[1] = fmaxf(fmaxf(e2[0], e2[1]), e2[2]);
                m2[2] = fmaxf(fmaxf(e2[1], e2[2]), e2[3]);
                m2[3] = fmaxf(fmaxf(e2[2], e2[3]), er2);

                if (iy >= 6 && storer) {
                    // ---- NMS output at yo = y-3 (center row = e1) ----
                    const int yo = y - 3;
                    const bool irow = (yo > 0) && (yo < H - 1);
                    float r[4];
                    // side max of center row (excl center)
                    float sd0 = fmaxf(el1,   e1[1]);
                    float sd1 = fmaxf(e1[0], e1[2]);
                    float sd2 = fmaxf(e1[1], e1[3]);
                    float sd3 = fmaxf(e1[2], er1);
                    float nm0 = fmaxf(fmaxf(m0[0], m2[0]), sd0);
                    float nm1 = fmaxf(fmaxf(m0[1], m2[1]), sd1);
                    float nm2 = fmaxf(fmaxf(m0[2], m2[2]), sd2);
                    float nm3 = fmaxf(fmaxf(m0[3], m2[3]), sd3);
                    r[0] = (irow && icol[0] && (e1[0] < nm0)) ? 0.f : e1[0];
                    r[1] = (irow && icol[1] && (e1[1] < nm1)) ? 0.f : e1[1];
                    r[2] = (irow && icol[2] && (e1[2] < nm2)) ? 0.f : e1[2];
                    r[3] = (irow && icol[3] && (e1[3] < nm3)) ? 0.f : e1[3];
                    *reinterpret_cast<float4*>(op + (size_t)yo * W + c0) =
                        make_float4(r[0], r[1], r[2], r[3]);
                }
            }
        }
    }
}

extern "C" void kernel_launch(void* const* d_in, const int* in_sizes, int n_in,
                              void* d_out, int out_size)
{
    const float* img = (const float*)d_in[0];
    float* out = (float*)d_out;
    edge_kernel<<<NBLOCKS, 256>>>(img, out);
}

// round 6
// speedup vs baseline: 1.6298x; 1.1417x over previous
#include <cuda_runtime.h>
#include <math.h>

#define W  2048
#define H  2048
#define NIMG 16

#define STRIP_OUT 120            // output columns per warp strip
#define NSTRIPS   18             // ceil(2048/120)
#define ROWT      64             // output rows per warp job
#define NROWT     32             // 2048/64
#define WARPS_PER_BLOCK 8
#define NJOBS (NIMG * NROWT * NSTRIPS)          // 9216
#define NBLOCKS (NJOBS / WARPS_PER_BLOCK)       // 1152

__device__ __forceinline__ float4 ld_row(const float* __restrict__ im,
                                         int y, int c0, bool colok)
{
    if (!((unsigned)y < (unsigned)H) || !colok) return make_float4(0.f, 0.f, 0.f, 0.f);
    return *reinterpret_cast<const float4*>(im + (size_t)y * W + c0);
}

// One pipeline step. PH is a literal 0/1/2 so all %3 indices constant-fold and
// ptxas renames the rings instead of emitting shift MOVs.
// Phase contract at step y (phase PH):
//   h[PH]   = horiz [1,2,1] of input row y
//   p/q[PH] = horiz Sobel parts of smoothed row y-1
//   e[PH]   = edge magnitude row y-2
//   m[PH]   = inclusive 3-col row max of e row y-2
//   store   = NMS output row y-3
#define BODY(IY, PH, DO_SM, DO_E, DO_ST) do {                                     \
    const int y_ = ybase + (IY);                                                  \
    float4 cur = nx1; nx1 = nx2;                                                  \
    nx2 = ld_row(im, y_ + 2, c0, colok);                                          \
    {                                                                             \
        float inm1 = __shfl_up_sync(0xffffffffu, cur.w, 1);                       \
        float inp4 = __shfl_down_sync(0xffffffffu, cur.x, 1);                     \
        h[(PH)][0] = inm1  + 2.f*cur.x + cur.y;                                   \
        h[(PH)][1] = cur.x + 2.f*cur.y + cur.z;                                   \
        h[(PH)][2] = cur.y + 2.f*cur.z + cur.w;                                   \
        h[(PH)][3] = cur.z + 2.f*cur.w + inp4;                                    \
    }                                                                             \
    if (DO_SM) {                                                                  \
        const int ys_ = y_ - 1;                                                   \
        const float msk = ((unsigned)ys_ < (unsigned)H) ? colmul : 0.f;           \
        float sm[4];                                                              \
        _Pragma("unroll") for (int j = 0; j < 4; j++)                             \
            sm[j] = (h[((PH)+1)%3][j] + 2.f*h[((PH)+2)%3][j] + h[(PH)][j]) * msk; \
        float smm1 = __shfl_up_sync(0xffffffffu, sm[3], 1);                       \
        float smp4 = __shfl_down_sync(0xffffffffu, sm[0], 1);                     \
        p[(PH)][0] = sm[1] - smm1;  q[(PH)][0] = smm1  + 2.f*sm[0] + sm[1];       \
        p[(PH)][1] = sm[2] - sm[0]; q[(PH)][1] = sm[0] + 2.f*sm[1] + sm[2];       \
        p[(PH)][2] = sm[3] - sm[1]; q[(PH)][2] = sm[1] + 2.f*sm[2] + sm[3];       \
        p[(PH)][3] = smp4  - sm[2]; q[(PH)][3] = sm[2] + 2.f*sm[3] + smp4;        \
        if (DO_E) {                                                               \
            _Pragma("unroll") for (int j = 0; j < 4; j++) {                       \
                float gx = p[((PH)+1)%3][j] + 2.f*p[((PH)+2)%3][j] + p[(PH)][j];  \
                float gy = q[(PH)][j] - q[((PH)+1)%3][j];                         \
                e[(PH)][j] = sqrtf(gx*gx + gy*gy);                                \
            }                                                                     \
            float el = __shfl_up_sync(0xffffffffu, e[(PH)][3], 1);                \
            float er = __shfl_down_sync(0xffffffffu, e[(PH)][0], 1);              \
            m[(PH)][0] = fmaxf(fmaxf(el,         e[(PH)][0]), e[(PH)][1]);        \
            m[(PH)][1] = fmaxf(fmaxf(e[(PH)][0], e[(PH)][1]), e[(PH)][2]);        \
            m[(PH)][2] = fmaxf(fmaxf(e[(PH)][1], e[(PH)][2]), e[(PH)][3]);        \
            m[(PH)][3] = fmaxf(fmaxf(e[(PH)][2], e[(PH)][3]), er);                \
            if ((DO_ST) && storer) {                                              \
                const int yo_ = y_ - 3;                                           \
                const bool irow = (yo_ > 0) && (yo_ < H - 1);                     \
                float r[4];                                                       \
                _Pragma("unroll") for (int j = 0; j < 4; j++) {                   \
                    float c  = e[((PH)+2)%3][j];                                  \
                    /* inclusive 9-max: c < max9  <=>  c < max8-excl-center */    \
                    float nm = fmaxf(fmaxf(m[((PH)+1)%3][j], m[((PH)+2)%3][j]),   \
                                     m[(PH)][j]);                                 \
                    r[j] = (irow && icol[j] && (c < nm)) ? 0.f : c;               \
                }                                                                 \
                *reinterpret_cast<float4*>(op + (size_t)yo_ * W + c0) =           \
                    make_float4(r[0], r[1], r[2], r[3]);                          \
            }                                                                     \
        }                                                                         \
    }                                                                             \
} while (0)

__global__ __launch_bounds__(256, 3)
void edge_kernel(const float* __restrict__ img, float* __restrict__ out)
{
    const int lane = threadIdx.x & 31;
    const int warp = threadIdx.x >> 5;
    const int job  = blockIdx.x * WARPS_PER_BLOCK + warp;

    const int strip = job % NSTRIPS;
    const int t     = job / NSTRIPS;
    const int rowt  = t % NROWT;
    const int n     = t / NROWT;

    const int cb = strip * STRIP_OUT - 4;   // loaded column base (mult of 4)
    const int c0 = cb + lane * 4;
    const int y0 = rowt * ROWT;
    const int ybase = y0 - 3;

    const float* im = img + (size_t)n * H * W;
    float*       op = out + (size_t)n * H * W;

    const bool  colok  = (c0 >= 0) && (c0 < W);
    const bool  storer = (lane >= 1) && (lane <= 30) && colok;
    const float colmul = colok ? 0.0625f : 0.f;

    bool icol[4];
    #pragma unroll
    for (int j = 0; j < 4; j++)
        icol[j] = (c0 + j > 0) && (c0 + j < W - 1);

    float h[3][4], p[3][4], q[3][4], e[3][4], m[3][4];
    #pragma unroll
    for (int a = 0; a < 3; a++)
        #pragma unroll
        for (int j = 0; j < 4; j++) {
            h[a][j]=0.f; p[a][j]=0.f; q[a][j]=0.f; e[a][j]=0.f; m[a][j]=0.f;
        }

    // 2-deep row prefetch (MLP = 2)
    float4 nx1 = ld_row(im, ybase,     c0, colok);
    float4 nx2 = ld_row(im, ybase + 1, c0, colok);

    // ---- warmup: 7 specialized iterations (first store at iy = 6) ----
    BODY(0, 0, false, false, false);
    BODY(1, 1, false, false, false);
    BODY(2, 2, true,  false, false);
    BODY(3, 0, true,  false, false);
    BODY(4, 1, true,  true,  false);
    BODY(5, 2, true,  true,  false);
    BODY(6, 0, true,  true,  true);

    // ---- steady: iy = 7 .. 69 (63 iters = 21 x 3), phases (1,2,0) ----
    for (int base = 7; base < ROWT + 6; base += 3) {
        BODY(base + 0, 1, true, true, true);
        BODY(base + 1, 2, true, true, true);
        BODY(base + 2, 0, true, true, true);
    }
}

extern "C" void kernel_launch(void* const* d_in, const int* in_sizes, int n_in,
                              void* d_out, int out_size)
{
    const float* img = (const float*)d_in[0];
    float* out = (float*)d_out;
    edge_kernel<<<NBLOCKS, 256>>>(img, out);
}

// round 7
// speedup vs baseline: 1.8745x; 1.1501x over previous
#include <cuda_runtime.h>
#include <math.h>

#define W  2048
#define H  2048
#define NIMG 16

#define STRIP_OUT 120            // output columns per warp strip
#define NSTRIPS   18             // ceil(2048/120)
#define ROWT      64             // output rows per warp job
#define NROWT     32             // 2048/64
#define WARPS_PER_BLOCK 4
#define NTHREADS (WARPS_PER_BLOCK * 32)
#define NJOBS (NIMG * NROWT * NSTRIPS)          // 9216
#define NBLOCKS (NJOBS / WARPS_PER_BLOCK)       // 2304

__device__ __forceinline__ float4 ld_row(const float* __restrict__ im,
                                         int y, int c0, bool colok)
{
    if (!((unsigned)y < (unsigned)H) || !colok) return make_float4(0.f, 0.f, 0.f, 0.f);
    return *reinterpret_cast<const float4*>(im + (size_t)y * W + c0);
}

// Pipeline step at input row y = ybase + IY:
//   hc  = horiz [1,2,1] of input row y                  (2 shfl)
//   smc = (hB + 2*hA + hc) * msk   -> smoothed row y-1  (zero outside image)
//   vs  = smB + 2*smA + smc  (vert [1,2,1] @ row y-2)
//   vd  = smc - smB          (vert [-1,0,1] @ row y-2)
//   gx  = vs[x+1] - vs[x-1], gy = vd[x-1] + 2vd[x] + vd[x+1]   (4 shfl)
//   ec  = sqrt(gx^2+gy^2)  -> edge row y-2;  mc = incl. 3-col row max (2 shfl)
//   store: NMS @ row y-3 (center eA; nm = max(mB, mA, mc))
// End-of-body copies are renamed by ptxas in the unrolled straight-line code.
#define BODY(IY, DO_SM, DO_E, DO_ST) do {                                        \
    const int y_ = ybase + (IY);                                                 \
    float4 cur = nx1; nx1 = nx2;                                                 \
    nx2 = ld_row(im, y_ + 2, c0, colok);                                         \
    float hc[4];                                                                 \
    {                                                                            \
        float inm1 = __shfl_up_sync(0xffffffffu, cur.w, 1);                      \
        float inp4 = __shfl_down_sync(0xffffffffu, cur.x, 1);                    \
        hc[0] = inm1  + 2.f*cur.x + cur.y;                                       \
        hc[1] = cur.x + 2.f*cur.y + cur.z;                                       \
        hc[2] = cur.y + 2.f*cur.z + cur.w;                                       \
        hc[3] = cur.z + 2.f*cur.w + inp4;                                        \
    }                                                                            \
    if (DO_SM) {                                                                 \
        const float msk = ((unsigned)(y_ - 1) < (unsigned)H) ? colmul : 0.f;     \
        float smc[4];                                                            \
        _Pragma("unroll") for (int j = 0; j < 4; j++)                            \
            smc[j] = (hB[j] + 2.f*hA[j] + hc[j]) * msk;                          \
        if (DO_E) {                                                              \
            float vs[4], vd[4];                                                  \
            _Pragma("unroll") for (int j = 0; j < 4; j++) {                      \
                vs[j] = smB[j] + 2.f*smA[j] + smc[j];                            \
                vd[j] = smc[j] - smB[j];                                         \
            }                                                                    \
            float vsm1 = __shfl_up_sync(0xffffffffu, vs[3], 1);                  \
            float vsp4 = __shfl_down_sync(0xffffffffu, vs[0], 1);                \
            float vdm1 = __shfl_up_sync(0xffffffffu, vd[3], 1);                  \
            float vdp4 = __shfl_down_sync(0xffffffffu, vd[0], 1);                \
            float ec[4];                                                         \
            {                                                                    \
                float gx0 = vs[1] - vsm1,  gy0 = vdm1  + 2.f*vd[0] + vd[1];      \
                float gx1 = vs[2] - vs[0], gy1 = vd[0] + 2.f*vd[1] + vd[2];      \
                float gx2 = vs[3] - vs[1], gy2 = vd[1] + 2.f*vd[2] + vd[3];      \
                float gx3 = vsp4  - vs[2], gy3 = vd[2] + 2.f*vd[3] + vdp4;       \
                ec[0] = sqrtf(gx0*gx0 + gy0*gy0);                                \
                ec[1] = sqrtf(gx1*gx1 + gy1*gy1);                                \
                ec[2] = sqrtf(gx2*gx2 + gy2*gy2);                                \
                ec[3] = sqrtf(gx3*gx3 + gy3*gy3);                                \
            }                                                                    \
            float el = __shfl_up_sync(0xffffffffu, ec[3], 1);                    \
            float er = __shfl_down_sync(0xffffffffu, ec[0], 1);                  \
            float mc[4];                                                         \
            mc[0] = fmaxf(fmaxf(el,    ec[0]), ec[1]);                           \
            mc[1] = fmaxf(fmaxf(ec[0], ec[1]), ec[2]);                           \
            mc[2] = fmaxf(fmaxf(ec[1], ec[2]), ec[3]);                           \
            mc[3] = fmaxf(fmaxf(ec[2], ec[3]), er);                              \
            if ((DO_ST) && storer) {                                             \
                const int yo_ = y_ - 3;                                          \
                const bool irow = (yo_ > 0) && (yo_ < H - 1);                    \
                float r[4];                                                      \
                _Pragma("unroll") for (int j = 0; j < 4; j++) {                  \
                    /* inclusive 9-max equals exclusive 8-max for '<' test */    \
                    float nm = fmaxf(fmaxf(mB[j], mA[j]), mc[j]);                \
                    r[j] = (irow && icol[j] && (eA[j] < nm)) ? 0.f : eA[j];      \
                }                                                                \
                *reinterpret_cast<float4*>(op + (size_t)yo_ * W + c0) =          \
                    make_float4(r[0], r[1], r[2], r[3]);                         \
            }                                                                    \
            _Pragma("unroll") for (int j = 0; j < 4; j++) {                      \
                eA[j] = ec[j]; mB[j] = mA[j]; mA[j] = mc[j];                     \
            }                                                                    \
        }                                                                        \
        _Pragma("unroll") for (int j = 0; j < 4; j++) {                          \
            smB[j] = smA[j]; smA[j] = smc[j];                                    \
        }                                                                        \
    }                                                                            \
    _Pragma("unroll") for (int j = 0; j < 4; j++) {                              \
        hB[j] = hA[j]; hA[j] = hc[j];                                            \
    }                                                                            \
} while (0)

__global__ __launch_bounds__(NTHREADS, 8)
void edge_kernel(const float* __restrict__ img, float* __restrict__ out)
{
    const int lane = threadIdx.x & 31;
    const int warp = threadIdx.x >> 5;
    const int job  = blockIdx.x * WARPS_PER_BLOCK + warp;

    const int strip = job % NSTRIPS;
    const int t     = job / NSTRIPS;
    const int rowt  = t % NROWT;
    const int n     = t / NROWT;

    const int cb = strip * STRIP_OUT - 4;   // loaded column base (mult of 4)
    const int c0 = cb + lane * 4;
    const int y0 = rowt * ROWT;
    const int ybase = y0 - 3;

    const float* im = img + (size_t)n * H * W;
    float*       op = out + (size_t)n * H * W;

    const bool  colok  = (c0 >= 0) && (c0 < W);
    const bool  storer = (lane >= 1) && (lane <= 30) && colok;
    const float colmul = colok ? 0.0625f : 0.f;

    bool icol[4];
    #pragma unroll
    for (int j = 0; j < 4; j++)
        icol[j] = (c0 + j > 0) && (c0 + j < W - 1);

    float hA[4], hB[4], smA[4], smB[4], eA[4], mA[4], mB[4];
    #pragma unroll
    for (int j = 0; j < 4; j++) {
        hA[j]=hB[j]=0.f; smA[j]=smB[j]=0.f; eA[j]=0.f; mA[j]=mB[j]=0.f;
    }

    // 2-deep row prefetch (MLP = 2)
    float4 nx1 = ld_row(im, ybase,     c0, colok);
    float4 nx2 = ld_row(im, ybase + 1, c0, colok);

    // ---- warmup: 7 specialized iterations (first store at iy = 6) ----
    BODY(0, false, false, false);
    BODY(1, false, false, false);
    BODY(2, true,  false, false);
    BODY(3, true,  false, false);
    BODY(4, true,  true,  false);
    BODY(5, true,  true,  false);
    BODY(6, true,  true,  true);

    // ---- steady: iy = 7 .. 69 (63 iters = 21 x 3) ----
    for (int base = 7; base < ROWT + 6; base += 3) {
        BODY(base + 0, true, true, true);
        BODY(base + 1, true, true, true);
        BODY(base + 2, true, true, true);
    }
}

extern "C" void kernel_launch(void* const* d_in, const int* in_sizes, int n_in,
                              void* d_out, int out_size)
{
    const float* img = (const float*)d_in[0];
    float* out = (float*)d_out;
    edge_kernel<<<NBLOCKS, NTHREADS>>>(img, out);
}

// round 8
// speedup vs baseline: 2.4701x; 1.3177x over previous
#include <cuda_runtime.h>
#include <math.h>

#define W  2048
#define H  2048
#define NIMG 16

#define STRIP_OUT 120            // output columns per warp strip
#define NSTRIPS   18             // ceil(2048/120)
#define ROWT      64             // output rows per warp job
#define NROWT     32             // 2048/64
#define WARPS_PER_BLOCK 4
#define NTHREADS (WARPS_PER_BLOCK * 32)
#define NJOBS (NIMG * NROWT * NSTRIPS)          // 9216
#define NBLOCKS (NJOBS / WARPS_PER_BLOCK)       // 2304

__device__ __forceinline__ float fsqrt_fast(float x)
{
    float r;
    asm("sqrt.approx.f32 %0, %1;" : "=f"(r) : "f"(x));
    return r;
}

__device__ __forceinline__ float4 ld_row(const float* __restrict__ im,
                                         int y, int c0, bool colok)
{
    if (!((unsigned)y < (unsigned)H) || !colok) return make_float4(0.f, 0.f, 0.f, 0.f);
    return *reinterpret_cast<const float4*>(im + (size_t)y * W + c0);
}

// Pipeline step at input row y = ybase + IY (see R7 comment).
// NMS select is done by masking the neighborhood max with -inf at borders:
//   r = (e < nm_masked) ? 0 : e   — borders get nm=-inf so e passes through.
#define BODY(IY, DO_SM, DO_E, DO_ST) do {                                        \
    const int y_ = ybase + (IY);                                                 \
    float4 cur = nx1; nx1 = nx2;                                                 \
    nx2 = ld_row(im, y_ + 2, c0, colok);                                         \
    float hc[4];                                                                 \
    {                                                                            \
        float inm1 = __shfl_up_sync(0xffffffffu, cur.w, 1);                      \
        float inp4 = __shfl_down_sync(0xffffffffu, cur.x, 1);                    \
        hc[0] = inm1  + 2.f*cur.x + cur.y;                                       \
        hc[1] = cur.x + 2.f*cur.y + cur.z;                                       \
        hc[2] = cur.y + 2.f*cur.z + cur.w;                                       \
        hc[3] = cur.z + 2.f*cur.w + inp4;                                        \
    }                                                                            \
    if (DO_SM) {                                                                 \
        const float msk = ((unsigned)(y_ - 1) < (unsigned)H) ? colmul : 0.f;     \
        float smc[4];                                                            \
        _Pragma("unroll") for (int j = 0; j < 4; j++)                            \
            smc[j] = (hB[j] + 2.f*hA[j] + hc[j]) * msk;                          \
        if (DO_E) {                                                              \
            float vs[4], vd[4];                                                  \
            _Pragma("unroll") for (int j = 0; j < 4; j++) {                      \
                vs[j] = smB[j] + 2.f*smA[j] + smc[j];                            \
                vd[j] = smc[j] - smB[j];                                         \
            }                                                                    \
            float vsm1 = __shfl_up_sync(0xffffffffu, vs[3], 1);                  \
            float vsp4 = __shfl_down_sync(0xffffffffu, vs[0], 1);                \
            float vdm1 = __shfl_up_sync(0xffffffffu, vd[3], 1);                  \
            float vdp4 = __shfl_down_sync(0xffffffffu, vd[0], 1);                \
            float ec[4];                                                         \
            {                                                                    \
                float gx0 = vs[1] - vsm1,  gy0 = vdm1  + 2.f*vd[0] + vd[1];      \
                float gx1 = vs[2] - vs[0], gy1 = vd[0] + 2.f*vd[1] + vd[2];      \
                float gx2 = vs[3] - vs[1], gy2 = vd[1] + 2.f*vd[2] + vd[3];      \
                float gx3 = vsp4  - vs[2], gy3 = vd[2] + 2.f*vd[3] + vdp4;       \
                ec[0] = fsqrt_fast(gx0*gx0 + gy0*gy0);                           \
                ec[1] = fsqrt_fast(gx1*gx1 + gy1*gy1);                           \
                ec[2] = fsqrt_fast(gx2*gx2 + gy2*gy2);                           \
                ec[3] = fsqrt_fast(gx3*gx3 + gy3*gy3);                           \
            }                                                                    \
            float el = __shfl_up_sync(0xffffffffu, ec[3], 1);                    \
            float er = __shfl_down_sync(0xffffffffu, ec[0], 1);                  \
            float mc[4];                                                         \
            mc[0] = fmaxf(fmaxf(el,    ec[0]), ec[1]);                           \
            mc[1] = fmaxf(fmaxf(ec[0], ec[1]), ec[2]);                           \
            mc[2] = fmaxf(fmaxf(ec[1], ec[2]), ec[3]);                           \
            mc[3] = fmaxf(fmaxf(ec[2], ec[3]), er);                              \
            if ((DO_ST) && storer) {                                             \
                const int yo_ = y_ - 3;                                          \
                const float rowmsk = ((yo_ > 0) && (yo_ < H - 1)) ? 0.f : NEGINF;\
                float r[4];                                                      \
                _Pragma("unroll") for (int j = 0; j < 4; j++) {                  \
                    /* inclusive 9-max == exclusive 8-max for the '<' test */    \
                    float nm = fmaxf(fmaxf(mB[j], mA[j]), mc[j]);                \
                    nm += rowmsk + colmsk[j];  /* -inf at any border */          \
                    r[j] = (eA[j] < nm) ? 0.f : eA[j];                           \
                }                                                                \
                *reinterpret_cast<float4*>(op + (size_t)yo_ * W + c0) =          \
                    make_float4(r[0], r[1], r[2], r[3]);                         \
            }                                                                    \
            _Pragma("unroll") for (int j = 0; j < 4; j++) {                      \
                eA[j] = ec[j]; mB[j] = mA[j]; mA[j] = mc[j];                     \
            }                                                                    \
        }                                                                        \
        _Pragma("unroll") for (int j = 0; j < 4; j++) {                          \
            smB[j] = smA[j]; smA[j] = smc[j];                                    \
        }                                                                        \
    }                                                                            \
    _Pragma("unroll") for (int j = 0; j < 4; j++) {                              \
        hB[j] = hA[j]; hA[j] = hc[j];                                            \
    }                                                                            \
} while (0)

#define NEGINF (-__int_as_float(0x7f800000))

__global__ __launch_bounds__(NTHREADS, 8)
void edge_kernel(const float* __restrict__ img, float* __restrict__ out)
{
    const int lane = threadIdx.x & 31;
    const int warp = threadIdx.x >> 5;
    const int job  = blockIdx.x * WARPS_PER_BLOCK + warp;

    const int strip = job % NSTRIPS;
    const int t     = job / NSTRIPS;
    const int rowt  = t % NROWT;
    const int n     = t / NROWT;

    const int cb = strip * STRIP_OUT - 4;   // loaded column base (mult of 4)
    const int c0 = cb + lane * 4;
    const int y0 = rowt * ROWT;
    const int ybase = y0 - 3;

    const float* im = img + (size_t)n * H * W;
    float*       op = out + (size_t)n * H * W;

    const bool  colok  = (c0 >= 0) && (c0 < W);
    const bool  storer = (lane >= 1) && (lane <= 30) && colok;
    const float colmul = colok ? 0.0625f : 0.f;

    // 0 for interior columns, -inf for border columns (kills suppression there)
    float colmsk[4];
    #pragma unroll
    for (int j = 0; j < 4; j++)
        colmsk[j] = ((c0 + j > 0) && (c0 + j < W - 1)) ? 0.f : NEGINF;

    float hA[4], hB[4], smA[4], smB[4], eA[4], mA[4], mB[4];
    #pragma unroll
    for (int j = 0; j < 4; j++) {
        hA[j]=hB[j]=0.f; smA[j]=smB[j]=0.f; eA[j]=0.f; mA[j]=mB[j]=0.f;
    }

    // 2-deep row prefetch (MLP = 2)
    float4 nx1 = ld_row(im, ybase,     c0, colok);
    float4 nx2 = ld_row(im, ybase + 1, c0, colok);

    // ---- warmup: 7 specialized iterations (first store at iy = 6) ----
    BODY(0, false, false, false);
    BODY(1, false, false, false);
    BODY(2, true,  false, false);
    BODY(3, true,  false, false);
    BODY(4, true,  true,  false);
    BODY(5, true,  true,  false);
    BODY(6, true,  true,  true);

    // ---- steady: iy = 7 .. 69 (63 iters = 21 x 3) ----
    for (int base = 7; base < ROWT + 6; base += 3) {
        BODY(base + 0, true, true, true);
        BODY(base + 1, true, true, true);
        BODY(base + 2, true, true, true);
    }
}

extern "C" void kernel_launch(void* const* d_in, const int* in_sizes, int n_in,
                              void* d_out, int out_size)
{
    const float* img = (const float*)d_in[0];
    float* out = (float*)d_out;
    edge_kernel<<<NBLOCKS, NTHREADS>>>(img, out);
}

// round 9
// speedup vs baseline: 2.8257x; 1.1440x over previous
#include <cuda_runtime.h>
#include <math.h>

#define W  2048
#define H  2048
#define NIMG 16

#define STRIP_OUT 248            // output columns per warp strip (8/lane)
#define NSTRIPS   9              // ceil(2048/248)
#define ROWT      64             // output rows per warp job
#define NROWT     32             // 2048/64
#define WARPS_PER_BLOCK 4
#define NTHREADS (WARPS_PER_BLOCK * 32)
#define NJOBS (NIMG * NROWT * NSTRIPS)          // 4608
#define NBLOCKS (NJOBS / WARPS_PER_BLOCK)       // 1152

#define NEGINF (-__int_as_float(0x7f800000))

__device__ __forceinline__ float fsqrt_fast(float x)
{
    float r;
    asm("sqrt.approx.f32 %0, %1;" : "=f"(r) : "f"(x));
    return r;
}

__device__ __forceinline__ float4 ld4(const float* __restrict__ im,
                                      int y, int c, bool ok)
{
    if (!((unsigned)y < (unsigned)H) || !ok) return make_float4(0.f, 0.f, 0.f, 0.f);
    return *reinterpret_cast<const float4*>(im + (size_t)y * W + c);
}

// Pipeline step at input row y = ybase + IY, 8 columns per lane.
// hc = horiz [1,2,1]; smc = vert-gauss * mask (zero outside image);
// vs/vd = vertical Sobel partials; gx/gy via column halos; ec = magnitude;
// mc = inclusive 3-col row max; store = NMS at row y-3.
// 8 shuffles per body covering 8 output columns.
#define BODY(IY, DO_SM, DO_E, DO_ST) do {                                        \
    const int y_ = ybase + (IY);                                                 \
    float cur[8];                                                                \
    cur[0]=nx1a.x; cur[1]=nx1a.y; cur[2]=nx1a.z; cur[3]=nx1a.w;                  \
    cur[4]=nx1b.x; cur[5]=nx1b.y; cur[6]=nx1b.z; cur[7]=nx1b.w;                  \
    nx1a = nx2a; nx1b = nx2b;                                                    \
    nx2a = ld4(im, y_ + 2, c0,     okA);                                         \
    nx2b = ld4(im, y_ + 2, c0 + 4, okB);                                         \
    float hc[8];                                                                 \
    {                                                                            \
        float inm1 = __shfl_up_sync(0xffffffffu, cur[7], 1);                     \
        float inp8 = __shfl_down_sync(0xffffffffu, cur[0], 1);                   \
        hc[0] = inm1 + 2.f*cur[0] + cur[1];                                      \
        _Pragma("unroll") for (int j = 1; j < 7; j++)                            \
            hc[j] = cur[j-1] + 2.f*cur[j] + cur[j+1];                            \
        hc[7] = cur[6] + 2.f*cur[7] + inp8;                                      \
    }                                                                            \
    if (DO_SM) {                                                                 \
        const bool rowok = ((unsigned)(y_ - 1) < (unsigned)H);                   \
        const float mskA = rowok ? cmulA : 0.f;                                  \
        const float mskB = rowok ? cmulB : 0.f;                                  \
        float smc[8];                                                            \
        _Pragma("unroll") for (int j = 0; j < 4; j++)                            \
            smc[j] = (hB[j] + 2.f*hA[j] + hc[j]) * mskA;                         \
        _Pragma("unroll") for (int j = 4; j < 8; j++)                            \
            smc[j] = (hB[j] + 2.f*hA[j] + hc[j]) * mskB;                         \
        if (DO_E) {                                                              \
            float vs[8], vd[8];                                                  \
            _Pragma("unroll") for (int j = 0; j < 8; j++) {                      \
                vs[j] = smB[j] + 2.f*smA[j] + smc[j];                            \
                vd[j] = smc[j] - smB[j];                                         \
            }                                                                    \
            float vsm1 = __shfl_up_sync(0xffffffffu, vs[7], 1);                  \
            float vsp8 = __shfl_down_sync(0xffffffffu, vs[0], 1);                \
            float vdm1 = __shfl_up_sync(0xffffffffu, vd[7], 1);                  \
            float vdp8 = __shfl_down_sync(0xffffffffu, vd[0], 1);                \
            float ec[8];                                                         \
            {                                                                    \
                float gx, gy;                                                    \
                gx = vs[1] - vsm1; gy = vdm1 + 2.f*vd[0] + vd[1];                \
                ec[0] = fsqrt_fast(gx*gx + gy*gy);                               \
                _Pragma("unroll") for (int j = 1; j < 7; j++) {                  \
                    gx = vs[j+1] - vs[j-1];                                      \
                    gy = vd[j-1] + 2.f*vd[j] + vd[j+1];                          \
                    ec[j] = fsqrt_fast(gx*gx + gy*gy);                           \
                }                                                                \
                gx = vsp8 - vs[6]; gy = vd[6] + 2.f*vd[7] + vdp8;                \
                ec[7] = fsqrt_fast(gx*gx + gy*gy);                               \
            }                                                                    \
            float el = __shfl_up_sync(0xffffffffu, ec[7], 1);                    \
            float er = __shfl_down_sync(0xffffffffu, ec[0], 1);                  \
            float mc[8];                                                         \
            mc[0] = fmaxf(fmaxf(el, ec[0]), ec[1]);                              \
            _Pragma("unroll") for (int j = 1; j < 7; j++)                        \
                mc[j] = fmaxf(fmaxf(ec[j-1], ec[j]), ec[j+1]);                   \
            mc[7] = fmaxf(fmaxf(ec[6], ec[7]), er);                              \
            if (DO_ST) {                                                         \
                const int yo_ = y_ - 3;                                          \
                const float rowmsk = ((yo_ > 0) && (yo_ < H-1)) ? 0.f : NEGINF;  \
                float r[8];                                                      \
                _Pragma("unroll") for (int j = 0; j < 8; j++) {                  \
                    float nm = fmaxf(fmaxf(mRB[j], mRA[j]), mc[j]);              \
                    nm += rowmsk + colmsk[j];                                    \
                    r[j] = (eA[j] < nm) ? 0.f : eA[j];                           \
                }                                                                \
                if (storerA)                                                     \
                    *reinterpret_cast<float4*>(op + (size_t)yo_ * W + c0) =      \
                        make_float4(r[0], r[1], r[2], r[3]);                     \
                if (storerB)                                                     \
                    *reinterpret_cast<float4*>(op + (size_t)yo_ * W + c0 + 4) =  \
                        make_float4(r[4], r[5], r[6], r[7]);                     \
            }                                                                    \
            _Pragma("unroll") for (int j = 0; j < 8; j++) {                      \
                eA[j] = ec[j]; mRB[j] = mRA[j]; mRA[j] = mc[j];                  \
            }                                                                    \
        }                                                                        \
        _Pragma("unroll") for (int j = 0; j < 8; j++) {                          \
            smB[j] = smA[j]; smA[j] = smc[j];                                    \
        }                                                                        \
    }                                                                            \
    _Pragma("unroll") for (int j = 0; j < 8; j++) {                              \
        hB[j] = hA[j]; hA[j] = hc[j];                                            \
    }                                                                            \
} while (0)

__global__ __launch_bounds__(NTHREADS, 4)
void edge_kernel(const float* __restrict__ img, float* __restrict__ out)
{
    const int lane = threadIdx.x & 31;
    const int warp = threadIdx.x >> 5;
    const int job  = blockIdx.x * WARPS_PER_BLOCK + warp;

    const int strip = job % NSTRIPS;
    const int t     = job / NSTRIPS;
    const int rowt  = t % NROWT;
    const int n     = t / NROWT;

    const int cb = strip * STRIP_OUT - 4;   // loaded column base (mult of 4)
    const int c0 = cb + lane * 8;           // this lane's first column
    const int y0 = rowt * ROWT;
    const int ybase = y0 - 3;

    const float* im = img + (size_t)n * H * W;
    float*       op = out + (size_t)n * H * W;

    // per-float4-group validity (groups are 4-aligned; W % 4 == 0)
    const bool okA = (c0     >= 0) && (c0     < W);
    const bool okB = (c0 + 4 >= 0) && (c0 + 4 < W);
    const float cmulA = okA ? 0.0625f : 0.f;
    const float cmulB = okB ? 0.0625f : 0.f;

    // stores: warp outputs cols cb+4 .. cb+251
    const bool storerA = (lane > 0)  && okA;
    const bool storerB = (lane < 31) && okB;

    // 0 interior, -inf at global col borders (kills suppression there)
    float colmsk[8];
    #pragma unroll
    for (int j = 0; j < 8; j++)
        colmsk[j] = ((c0 + j > 0) && (c0 + j < W - 1)) ? 0.f : NEGINF;

    float hA[8], hB[8], smA[8], smB[8], eA[8], mRA[8], mRB[8];
    #pragma unroll
    for (int j = 0; j < 8; j++) {
        hA[j]=hB[j]=0.f; smA[j]=smB[j]=0.f; eA[j]=0.f; mRA[j]=mRB[j]=0.f;
    }

    // 2-deep row prefetch (2 x 2 independent float4 loads in flight)
    float4 nx1a = ld4(im, ybase,     c0,     okA);
    float4 nx1b = ld4(im, ybase,     c0 + 4, okB);
    float4 nx2a = ld4(im, ybase + 1, c0,     okA);
    float4 nx2b = ld4(im, ybase + 1, c0 + 4, okB);

    // ---- warmup: 8 specialized iterations (first store at iy = 6) ----
    BODY(0, false, false, false);
    BODY(1, false, false, false);
    BODY(2, true,  false, false);
    BODY(3, true,  false, false);
    BODY(4, true,  true,  false);
    BODY(5, true,  true,  false);
    BODY(6, true,  true,  true);
    BODY(7, true,  true,  true);

    // ---- steady: iy = 8 .. 69 (62 iters = 31 x 2; ring depth 2 => unroll 2) ----
    for (int base = 8; base < ROWT + 6; base += 2) {
        BODY(base + 0, true, true, true);
        BODY(base + 1, true, true, true);
    }
}

extern "C" void kernel_launch(void* const* d_in, const int* in_sizes, int n_in,
                              void* d_out, int out_size)
{
    const float* img = (const float*)d_in[0];
    float* out = (float*)d_out;
    edge_kernel<<<NBLOCKS, NTHREADS>>>(img, out);
}

// round 10
// speedup vs baseline: 2.9255x; 1.0353x over previous
#include <cuda_runtime.h>
#include <math.h>

#define W  2048
#define H  2048
#define NIMG 16

#define STRIP_OUT 248            // output columns per warp strip (8/lane)
#define NSTRIPS   9              // ceil(2048/248)
#define ROWT      128            // output rows per warp job
#define NROWT     16             // 2048/128
#define WARPS_PER_BLOCK 4
#define NTHREADS (WARPS_PER_BLOCK * 32)
#define NJOBS (NIMG * NROWT * NSTRIPS)          // 2304
#define NBLOCKS (NJOBS / WARPS_PER_BLOCK)       // 576  -> single wave @ 4 blk/SM

#define NEGINF (-__int_as_float(0x7f800000))

__device__ __forceinline__ float fsqrt_fast(float x)
{
    float r;
    asm("sqrt.approx.f32 %0, %1;" : "=f"(r) : "f"(x));
    return r;
}

__device__ __forceinline__ float4 ld4(const float* __restrict__ im,
                                      int y, int c, bool ok)
{
    if (!((unsigned)y < (unsigned)H) || !ok) return make_float4(0.f, 0.f, 0.f, 0.f);
    return *reinterpret_cast<const float4*>(im + (size_t)y * W + c);
}

// Pipeline step at input row y = ybase + IY, 8 columns per lane.
#define BODY(IY, DO_SM, DO_E, DO_ST) do {                                        \
    const int y_ = ybase + (IY);                                                 \
    float cur[8];                                                                \
    cur[0]=nx1a.x; cur[1]=nx1a.y; cur[2]=nx1a.z; cur[3]=nx1a.w;                  \
    cur[4]=nx1b.x; cur[5]=nx1b.y; cur[6]=nx1b.z; cur[7]=nx1b.w;                  \
    nx1a = nx2a; nx1b = nx2b;                                                    \
    nx2a = ld4(im, y_ + 2, c0,     okA);                                         \
    nx2b = ld4(im, y_ + 2, c0 + 4, okB);                                         \
    float hc[8];                                                                 \
    {                                                                            \
        float inm1 = __shfl_up_sync(0xffffffffu, cur[7], 1);                     \
        float inp8 = __shfl_down_sync(0xffffffffu, cur[0], 1);                   \
        hc[0] = inm1 + 2.f*cur[0] + cur[1];                                      \
        _Pragma("unroll") for (int j = 1; j < 7; j++)                            \
            hc[j] = cur[j-1] + 2.f*cur[j] + cur[j+1];                            \
        hc[7] = cur[6] + 2.f*cur[7] + inp8;                                      \
    }                                                                            \
    if (DO_SM) {                                                                 \
        const bool rowok = ((unsigned)(y_ - 1) < (unsigned)H);                   \
        const float mskA = rowok ? cmulA : 0.f;                                  \
        const float mskB = rowok ? cmulB : 0.f;                                  \
        float smc[8];                                                            \
        _Pragma("unroll") for (int j = 0; j < 4; j++)                            \
            smc[j] = (hB[j] + 2.f*hA[j] + hc[j]) * mskA;                         \
        _Pragma("unroll") for (int j = 4; j < 8; j++)                            \
            smc[j] = (hB[j] + 2.f*hA[j] + hc[j]) * mskB;                         \
        if (DO_E) {                                                              \
            float vs[8], vd[8];                                                  \
            _Pragma("unroll") for (int j = 0; j < 8; j++) {                      \
                vs[j] = smB[j] + 2.f*smA[j] + smc[j];                            \
                vd[j] = smc[j] - smB[j];                                         \
            }                                                                    \
            float vsm1 = __shfl_up_sync(0xffffffffu, vs[7], 1);                  \
            float vsp8 = __shfl_down_sync(0xffffffffu, vs[0], 1);                \
            float vdm1 = __shfl_up_sync(0xffffffffu, vd[7], 1);                  \
            float vdp8 = __shfl_down_sync(0xffffffffu, vd[0], 1);                \
            float ec[8];                                                         \
            {                                                                    \
                float gx, gy;                                                    \
                gx = vs[1] - vsm1; gy = vdm1 + 2.f*vd[0] + vd[1];                \
                ec[0] = fsqrt_fast(gx*gx + gy*gy);                               \
                _Pragma("unroll") for (int j = 1; j < 7; j++) {                  \
                    gx = vs[j+1] - vs[j-1];                                      \
                    gy = vd[j-1] + 2.f*vd[j] + vd[j+1];                          \
                    ec[j] = fsqrt_fast(gx*gx + gy*gy);                           \
                }                                                                \
                gx = vsp8 - vs[6]; gy = vd[6] + 2.f*vd[7] + vdp8;                \
                ec[7] = fsqrt_fast(gx*gx + gy*gy);                               \
            }                                                                    \
            float el = __shfl_up_sync(0xffffffffu, ec[7], 1);                    \
            float er = __shfl_down_sync(0xffffffffu, ec[0], 1);                  \
            float mc[8];                                                         \
            mc[0] = fmaxf(fmaxf(el, ec[0]), ec[1]);                              \
            _Pragma("unroll") for (int j = 1; j < 7; j++)                        \
                mc[j] = fmaxf(fmaxf(ec[j-1], ec[j]), ec[j+1]);                   \
            mc[7] = fmaxf(fmaxf(ec[6], ec[7]), er);                              \
            if (DO_ST) {                                                         \
                const int yo_ = y_ - 3;                                          \
                float r[8];                                                      \
                if ((yo_ > 0) && (yo_ < H - 1)) {   /* warp-uniform branch */    \
                    _Pragma("unroll") for (int j = 0; j < 8; j++) {              \
                        float nm = fmaxf(fmaxf(mRB[j], mRA[j]), mc[j])           \
                                   + colmsk[j];                                  \
                        r[j] = (eA[j] < nm) ? 0.f : eA[j];                       \
                    }                                                            \
                } else {                                                         \
                    _Pragma("unroll") for (int j = 0; j < 8; j++)                \
                        r[j] = eA[j];                                            \
                }                                                                \
                if (storerA)                                                     \
                    *reinterpret_cast<float4*>(op + (size_t)yo_ * W + c0) =      \
                        make_float4(r[0], r[1], r[2], r[3]);                     \
                if (storerB)                                                     \
                    *reinterpret_cast<float4*>(op + (size_t)yo_ * W + c0 + 4) =  \
                        make_float4(r[4], r[5], r[6], r[7]);                     \
            }                                                                    \
            _Pragma("unroll") for (int j = 0; j < 8; j++) {                      \
                eA[j] = ec[j]; mRB[j] = mRA[j]; mRA[j] = mc[j];                  \
            }                                                                    \
        }                                                                        \
        _Pragma("unroll") for (int j = 0; j < 8; j++) {                          \
            smB[j] = smA[j]; smA[j] = smc[j];                                    \
        }                                                                        \
    }                                                                            \
    _Pragma("unroll") for (int j = 0; j < 8; j++) {                              \
        hB[j] = hA[j]; hA[j] = hc[j];                                            \
    }                                                                            \
} while (0)

__global__ __launch_bounds__(NTHREADS, 4)
void edge_kernel(const float* __restrict__ img, float* __restrict__ out)
{
    const int lane = threadIdx.x & 31;
    const int warp = threadIdx.x >> 5;
    const int job  = blockIdx.x * WARPS_PER_BLOCK + warp;

    const int strip = job % NSTRIPS;
    const int t     = job / NSTRIPS;
    const int rowt  = t % NROWT;
    const int n     = t / NROWT;

    const int cb = strip * STRIP_OUT - 4;   // loaded column base (mult of 4)
    const int c0 = cb + lane * 8;           // this lane's first column
    const int y0 = rowt * ROWT;
    const int ybase = y0 - 3;

    const float* im = img + (size_t)n * H * W;
    float*       op = out + (size_t)n * H * W;

    // per-float4-group validity (groups are 4-aligned; W % 4 == 0)
    const bool okA = (c0     >= 0) && (c0     < W);
    const bool okB = (c0 + 4 >= 0) && (c0 + 4 < W);
    const float cmulA = okA ? 0.0625f : 0.f;
    const float cmulB = okB ? 0.0625f : 0.f;

    // stores: warp outputs cols cb+4 .. cb+251
    const bool storerA = (lane > 0)  && okA;
    const bool storerB = (lane < 31) && okB;

    // 0 interior, -inf at global col borders (kills suppression there)
    float colmsk[8];
    #pragma unroll
    for (int j = 0; j < 8; j++)
        colmsk[j] = ((c0 + j > 0) && (c0 + j < W - 1)) ? 0.f : NEGINF;

    float hA[8], hB[8], smA[8], smB[8], eA[8], mRA[8], mRB[8];
    #pragma unroll
    for (int j = 0; j < 8; j++) {
        hA[j]=hB[j]=0.f; smA[j]=smB[j]=0.f; eA[j]=0.f; mRA[j]=mRB[j]=0.f;
    }

    // 2-deep row prefetch (4 independent float4 loads in flight)
    float4 nx1a = ld4(im, ybase,     c0,     okA);
    float4 nx1b = ld4(im, ybase,     c0 + 4, okB);
    float4 nx2a = ld4(im, ybase + 1, c0,     okA);
    float4 nx2b = ld4(im, ybase + 1, c0 + 4, okB);

    // ---- warmup: 8 specialized iterations (first store at iy = 6) ----
    BODY(0, false, false, false);
    BODY(1, false, false, false);
    BODY(2, true,  false, false);
    BODY(3, true,  false, false);
    BODY(4, true,  true,  false);
    BODY(5, true,  true,  false);
    BODY(6, true,  true,  true);
    BODY(7, true,  true,  true);

    // ---- steady: iy = 8 .. ROWT+5 (126 iters = 63 x 2) ----
    for (int base = 8; base < ROWT + 6; base += 2) {
        BODY(base + 0, true, true, true);
        BODY(base + 1, true, true, true);
    }
}

extern "C" void kernel_launch(void* const* d_in, const int* in_sizes, int n_in,
                              void* d_out, int out_size)
{
    const float* img = (const float*)d_in[0];
    float* out = (float*)d_out;
    edge_kernel<<<NBLOCKS, NTHREADS>>>(img, out);
}